// round 1
// baseline (speedup 1.0000x reference)
#include <cuda_runtime.h>
#include <math.h>

#define LL   4096
#define DM   96
#define DI   192
#define DSN  16
#define DRNK 6
#define KDIR 4

// ---- scratch (no cudaMalloc allowed) ----
__device__ float g_xx[LL*DI];        // [p][d] pre-conv
__device__ float g_z[LL*DI];         // [p][d] gate branch
__device__ float g_xc[LL*DI];        // [p][d] conv+silu
__device__ float g_delta[KDIR*LL*DI];// [k][p][d]
__device__ float g_Bs[KDIR*LL*DSN];  // [k][p][n]
__device__ float g_Cs[KDIR*LL*DSN];  // [k][p][n]
__device__ float g_yk[KDIR*LL*DI];   // [k][p][d] per-direction out_y
__device__ float g_inT[DM*384];      // [c][e]   transposed in_proj_w
__device__ float g_WpT[DI*152];      // [c][row] transposed x_proj_w (rows = k*38+cc)
__device__ float g_dtwT[DRNK*768];   // [r][kd]  transposed dt_w
__device__ float g_opT[DI*DM];       // [d][c]   transposed out_proj_w

// ---------------- K0: weight transposes ----------------
__global__ void k0_prep(const float* __restrict__ in_w, const float* __restrict__ xp_w,
                        const float* __restrict__ dt_w, const float* __restrict__ op_w) {
    int t = blockIdx.x * blockDim.x + threadIdx.x;
    int stride = gridDim.x * blockDim.x;
    for (int i = t; i < 384*DM; i += stride) {
        int e = i / DM, c = i % DM;
        g_inT[c*384 + e] = in_w[e*DM + c];
    }
    for (int i = t; i < 152*DI; i += stride) {
        int row = i / DI, c = i % DI;
        g_WpT[c*152 + row] = xp_w[row*DI + c];
    }
    for (int i = t; i < 768*DRNK; i += stride) {
        int kd = i / DRNK, r = i % DRNK;
        g_dtwT[r*768 + kd] = dt_w[kd*DRNK + r];
    }
    for (int i = t; i < DM*DI; i += stride) {
        int c = i / DI, d = i % DI;
        g_opT[d*DM + c] = op_w[c*DI + d];
    }
}

// ---------------- K1: in_proj (xz = x @ W^T), 16 positions/block ----------------
__global__ void __launch_bounds__(384) k1_inproj(const float* __restrict__ x) {
    __shared__ float xT[DM*20];   // [c][p] padded stride 20 (16B-aligned float4 rows)
    int p0 = blockIdx.x * 16;
    int t = threadIdx.x;
    for (int i = t; i < DM*16; i += 384) {
        int c = i % DM, p = i / DM;
        xT[c*20 + p] = x[(p0+p)*DM + c];
    }
    __syncthreads();
    int r = t;   // 384 output rows exactly
    float acc[16];
    #pragma unroll
    for (int j = 0; j < 16; j++) acc[j] = 0.f;
    for (int c = 0; c < DM; c++) {
        float w = g_inT[c*384 + r];
        const float4* xv = (const float4*)&xT[c*20];
        #pragma unroll
        for (int j4 = 0; j4 < 4; j4++) {
            float4 v = xv[j4];
            acc[j4*4+0] = fmaf(w, v.x, acc[j4*4+0]);
            acc[j4*4+1] = fmaf(w, v.y, acc[j4*4+1]);
            acc[j4*4+2] = fmaf(w, v.z, acc[j4*4+2]);
            acc[j4*4+3] = fmaf(w, v.w, acc[j4*4+3]);
        }
    }
    float* dst = (r < DI) ? g_xx : g_z;
    int rr = (r < DI) ? r : (r - DI);
    #pragma unroll
    for (int p = 0; p < 16; p++) dst[(p0+p)*DI + rr] = acc[p];
}

// ---------------- K2: depthwise 3x3 conv + bias + SiLU ----------------
__global__ void __launch_bounds__(256) k2_conv(const float* __restrict__ cw,
                                               const float* __restrict__ cb) {
    int g = blockIdx.x * 256 + threadIdx.x;
    if (g >= LL*DI) return;
    int d = g % DI;
    int p = g / DI;
    int h = p >> 6, w = p & 63;
    float acc = cb[d];
    #pragma unroll
    for (int i = 0; i < 3; i++) {
        int hh = h + i - 1;
        if ((unsigned)hh < 64u) {
            #pragma unroll
            for (int j = 0; j < 3; j++) {
                int ww = w + j - 1;
                if ((unsigned)ww < 64u)
                    acc = fmaf(g_xx[(hh*64+ww)*DI + d], cw[d*9 + i*3 + j], acc);
            }
        }
    }
    float s = acc / (1.f + __expf(-acc));
    g_xc[p*DI + d] = s;
}

// ---------------- K3: per-position projections -> B, C, delta ----------------
// Stage1: v[k*38+cc] = x_proj_w[k] @ xc[p]   (152 rows of length 192)
// Stage2: delta[k,d] = softplus(dt_w[k,d,:] . v[k,0:6] + dt_b)   (rank-6!)
__global__ void __launch_bounds__(256) k3_proj(const float* __restrict__ dt_b) {
    __shared__ float xT[DI*20];      // [c][p] stride 20
    __shared__ float vbuf[152*16];   // [row][p]
    int p0 = blockIdx.x * 16;
    int t = threadIdx.x;
    for (int i = t; i < DI*16; i += 256) {
        int c = i % DI, p = i / DI;
        xT[c*20 + p] = g_xc[(p0+p)*DI + c];
    }
    __syncthreads();
    if (t < 152) {
        float acc[16];
        #pragma unroll
        for (int j = 0; j < 16; j++) acc[j] = 0.f;
        for (int c = 0; c < DI; c++) {
            float w = g_WpT[c*152 + t];
            const float4* xv = (const float4*)&xT[c*20];
            #pragma unroll
            for (int j4 = 0; j4 < 4; j4++) {
                float4 v = xv[j4];
                acc[j4*4+0] = fmaf(w, v.x, acc[j4*4+0]);
                acc[j4*4+1] = fmaf(w, v.y, acc[j4*4+1]);
                acc[j4*4+2] = fmaf(w, v.z, acc[j4*4+2]);
                acc[j4*4+3] = fmaf(w, v.w, acc[j4*4+3]);
            }
        }
        #pragma unroll
        for (int p = 0; p < 16; p++) vbuf[t*16 + p] = acc[p];
        int k = t / 38, cc = t % 38;
        if (cc >= 6 && cc < 22) {
            #pragma unroll
            for (int p = 0; p < 16; p++)
                g_Bs[(k*LL + p0+p)*DSN + (cc-6)] = acc[p];
        } else if (cc >= 22) {
            #pragma unroll
            for (int p = 0; p < 16; p++)
                g_Cs[(k*LL + p0+p)*DSN + (cc-22)] = acc[p];
        }
    }
    __syncthreads();
    for (int r = t; r < 768; r += 256) {
        int k = r / DI, d = r % DI;
        float acc[16];
        #pragma unroll
        for (int j = 0; j < 16; j++) acc[j] = 0.f;
        #pragma unroll
        for (int c = 0; c < DRNK; c++) {
            float w = g_dtwT[c*768 + r];
            const float* vv = &vbuf[(k*38 + c)*16];
            #pragma unroll
            for (int p = 0; p < 16; p++) acc[p] = fmaf(w, vv[p], acc[p]);
        }
        float b = dt_b[r];
        #pragma unroll
        for (int p = 0; p < 16; p++) {
            float xv = acc[p] + b;
            float sp = (xv > 20.f) ? xv : log1pf(__expf(xv));
            g_delta[(k*LL + p0+p)*DI + d] = sp;
        }
    }
}

// ---------------- K4: selective scan ----------------
// half-warp per (k,d) channel: lane n = state; 16-step register prefetch chunks.
// Read position == write position == perm_k(l) for every direction.
__global__ void __launch_bounds__(32) k4_scan(const float* __restrict__ A_logs,
                                              const float* __restrict__ Ds) {
    int bid  = blockIdx.x;
    int lane = threadIdx.x;
    int half = lane >> 4;
    int n    = lane & 15;
    int kd   = bid*2 + half;          // both halves share the same k (192 even)
    int k    = kd / DI;
    int d    = kd % DI;
    float A_n = -__expf(A_logs[kd*DSN + n]);
    float Dv  = Ds[kd];

    const float* dptr = &g_delta[(size_t)k*LL*DI + d];  // + p*DI
    const float* xptr = &g_xc[d];                       // + p*DI
    const float* bptr = &g_Bs[(size_t)k*LL*DSN + n];    // + p*DSN
    const float* cptr = &g_Cs[(size_t)k*LL*DSN + n];
    float*       yptr = &g_yk[(size_t)k*LL*DI + d];

    auto posf = [&](int l) -> int {
        int ll = (k >= 2) ? (LL - 1 - l) : l;
        if (k & 1) return ((ll & 63) << 6) | (ll >> 6);
        return ll;
    };

    const int CH = 16;
    float cd[CH], cx[CH], cbv[CH], ccv[CH];
    #pragma unroll
    for (int j = 0; j < CH; j++) {
        int p = posf(j);
        cd[j]  = dptr[p*DI];
        cx[j]  = xptr[p*DI];
        cbv[j] = bptr[p*DSN];
        ccv[j] = cptr[p*DSN];
    }

    float h = 0.f;
    for (int c0 = 0; c0 < LL; c0 += CH) {
        float nd[CH], nx[CH], nb[CH], nc[CH];
        bool more = (c0 + CH) < LL;
        if (more) {
            #pragma unroll
            for (int j = 0; j < CH; j++) {
                int p = posf(c0 + CH + j);
                nd[j] = dptr[p*DI];
                nx[j] = xptr[p*DI];
                nb[j] = bptr[p*DSN];
                nc[j] = cptr[p*DSN];
            }
        }
        #pragma unroll
        for (int j = 0; j < CH; j++) {
            float delta = cd[j];
            float xval  = cx[j];
            float dA = __expf(delta * A_n);
            h = fmaf(dA, h, delta * xval * cbv[j]);
            float part = h * ccv[j];
            part += __shfl_xor_sync(0xffffffffu, part, 8);
            part += __shfl_xor_sync(0xffffffffu, part, 4);
            part += __shfl_xor_sync(0xffffffffu, part, 2);
            part += __shfl_xor_sync(0xffffffffu, part, 1);
            if (n == 0) {
                int p = posf(c0 + j);
                yptr[p*DI] = part + Dv * xval;
            }
        }
        if (more) {
            #pragma unroll
            for (int j = 0; j < CH; j++) {
                cd[j] = nd[j]; cx[j] = nx[j]; cbv[j] = nb[j]; ccv[j] = nc[j];
            }
        }
    }
}

// ---------------- K5: combine 4 dirs + LayerNorm + SiLU gate + out_proj ----------------
__global__ void __launch_bounds__(512) k5_out(const float* __restrict__ ln_g,
                                              const float* __restrict__ ln_b,
                                              float* __restrict__ out) {
    __shared__ float ysm[16*200];  // [p][d] stride 200
    int p0 = blockIdx.x * 16;
    int t = threadIdx.x;
    for (int i = t; i < 16*DI; i += 512) {
        int p = i / DI, d = i % DI;
        size_t gi = (size_t)(p0+p)*DI + d;
        float y = g_yk[gi] + g_yk[(size_t)LL*DI + gi]
                + g_yk[(size_t)2*LL*DI + gi] + g_yk[(size_t)3*LL*DI + gi];
        ysm[p*200 + d] = y;
    }
    __syncthreads();
    {
        int wp = t >> 5, ln = t & 31;   // 16 warps == 16 positions
        float s = 0.f, s2 = 0.f;
        for (int d = ln; d < DI; d += 32) {
            float v = ysm[wp*200 + d];
            s += v; s2 += v*v;
        }
        #pragma unroll
        for (int o = 16; o; o >>= 1) {
            s  += __shfl_xor_sync(0xffffffffu, s,  o);
            s2 += __shfl_xor_sync(0xffffffffu, s2, o);
        }
        float mu   = s  * (1.f/DI);
        float var  = s2 * (1.f/DI) - mu*mu;
        float rstd = rsqrtf(var + 1e-5f);
        for (int d = ln; d < DI; d += 32) {
            float v = (ysm[wp*200 + d] - mu) * rstd * ln_g[d] + ln_b[d];
            float z = g_z[(p0+wp)*DI + d];
            float sz = z / (1.f + __expf(-z));
            ysm[wp*200 + d] = v * sz;
        }
    }
    __syncthreads();
    for (int task = t; task < 96*16; task += 512) {
        int row = task % 96, p = task / 96;
        float acc = 0.f;
        const float* g = &ysm[p*200];
        #pragma unroll 4
        for (int d = 0; d < DI; d++)
            acc = fmaf(g_opT[d*96 + row], g[d], acc);
        out[(p0+p)*96 + row] = acc;
    }
}

extern "C" void kernel_launch(void* const* d_in, const int* in_sizes, int n_in,
                              void* d_out, int out_size) {
    const float* x         = (const float*)d_in[0];
    const float* in_proj_w = (const float*)d_in[1];
    const float* conv_w    = (const float*)d_in[2];
    const float* conv_b    = (const float*)d_in[3];
    const float* x_proj_w  = (const float*)d_in[4];
    const float* dt_w      = (const float*)d_in[5];
    const float* dt_b      = (const float*)d_in[6];
    const float* A_logs    = (const float*)d_in[7];
    const float* Ds        = (const float*)d_in[8];
    const float* ln_g      = (const float*)d_in[9];
    const float* ln_b      = (const float*)d_in[10];
    const float* out_proj  = (const float*)d_in[11];
    float* out = (float*)d_out;

    k0_prep<<<64, 256>>>(in_proj_w, x_proj_w, dt_w, out_proj);
    k1_inproj<<<LL/16, 384>>>(x);
    k2_conv<<<(LL*DI)/256, 256>>>(conv_w, conv_b);
    k3_proj<<<LL/16, 256>>>(dt_b);
    k4_scan<<<384, 32>>>(A_logs, Ds);
    k5_out<<<LL/16, 512>>>(ln_g, ln_b, out);
    (void)in_sizes; (void)n_in; (void)out_size;
}

// round 3
// speedup vs baseline: 2.5799x; 2.5799x over previous
#include <cuda_runtime.h>
#include <math.h>

#define LL   4096
#define DM   96
#define DI   192
#define DSN  16
#define DRNK 6
#define KDIR 4
#define NSEG 16
#define SEGL (LL/NSEG)   // 256

// ---- scratch (no cudaMalloc allowed) ----
__device__ float g_xx[LL*DI];          // [p][d] pre-conv
__device__ float g_z[LL*DI];           // [p][d] gate branch
__device__ float g_xc[LL*DI];          // [p][d] conv+silu
__device__ float g_dT [KDIR*DI*LL];    // [k][d][p] delta (position-indexed)
__device__ float g_dxT[KDIR*DI*LL];    // [k][d][p] delta*x
__device__ float g_DxT[KDIR*DI*LL];    // [k][d][p] D*x
__device__ float g_Bs[KDIR*LL*DSN];    // [k][l][n]  scan-ordered
__device__ float g_Cs[KDIR*LL*DSN];    // [k][l][n]  scan-ordered
__device__ float g_yk[KDIR*DI*LL];     // [k][d][p] per-direction out_y (position-indexed)
__device__ float g_inT[DM*384];        // [c][e]   transposed in_proj_w
__device__ float g_WpT[DI*152];        // [c][row] transposed x_proj_w (rows = k*38+cc)
__device__ float g_dtwT[DRNK*768];     // [r][kd]  transposed dt_w
__device__ float g_opT[DI*DM];         // [d][c]   transposed out_proj_w

__device__ __forceinline__ float ex2f(float x) {
    float r; asm("ex2.approx.ftz.f32 %0, %1;" : "=f"(r) : "f"(x)); return r;
}
// inverse of scan permutation: spatial position p -> scan index l for direction k
__device__ __forceinline__ int invperm(int k, int p) {
    int t = ((p & 63) << 6) | (p >> 6);
    int l = (k & 1) ? t : p;
    return (k >= 2) ? (LL - 1 - l) : l;
}

// ---------------- K0: weight transposes ----------------
__global__ void k0_prep(const float* __restrict__ in_w, const float* __restrict__ xp_w,
                        const float* __restrict__ dt_w, const float* __restrict__ op_w) {
    int t = blockIdx.x * blockDim.x + threadIdx.x;
    int stride = gridDim.x * blockDim.x;
    for (int i = t; i < 384*DM; i += stride) {
        int e = i / DM, c = i % DM;
        g_inT[c*384 + e] = in_w[e*DM + c];
    }
    for (int i = t; i < 152*DI; i += stride) {
        int row = i / DI, c = i % DI;
        g_WpT[c*152 + row] = xp_w[row*DI + c];
    }
    for (int i = t; i < 768*DRNK; i += stride) {
        int kd = i / DRNK, r = i % DRNK;
        g_dtwT[r*768 + kd] = dt_w[kd*DRNK + r];
    }
    for (int i = t; i < DM*DI; i += stride) {
        int c = i / DI, d = i % DI;
        g_opT[d*DM + c] = op_w[c*DI + d];
    }
}

// ---------------- K1: in_proj, 8 positions/block ----------------
__global__ void __launch_bounds__(384) k1_inproj(const float* __restrict__ x) {
    __shared__ float xT[DM*20];   // [c][p] stride 20 (16B aligned rows)
    int p0 = blockIdx.x * 8;
    int t = threadIdx.x;
    for (int i = t; i < DM*8; i += 384) {
        int c = i % DM, p = i / DM;
        xT[c*20 + p] = x[(p0+p)*DM + c];
    }
    __syncthreads();
    int r = t;   // 384 output rows exactly
    float acc[8];
    #pragma unroll
    for (int j = 0; j < 8; j++) acc[j] = 0.f;
    for (int c = 0; c < DM; c++) {
        float w = g_inT[c*384 + r];
        const float4* xv = (const float4*)&xT[c*20];
        #pragma unroll
        for (int j4 = 0; j4 < 2; j4++) {
            float4 v = xv[j4];
            acc[j4*4+0] = fmaf(w, v.x, acc[j4*4+0]);
            acc[j4*4+1] = fmaf(w, v.y, acc[j4*4+1]);
            acc[j4*4+2] = fmaf(w, v.z, acc[j4*4+2]);
            acc[j4*4+3] = fmaf(w, v.w, acc[j4*4+3]);
        }
    }
    float* dst = (r < DI) ? g_xx : g_z;
    int rr = (r < DI) ? r : (r - DI);
    #pragma unroll
    for (int p = 0; p < 8; p++) dst[(p0+p)*DI + rr] = acc[p];
}

// ---------------- K2: depthwise 3x3 conv + bias + SiLU ----------------
__global__ void __launch_bounds__(256) k2_conv(const float* __restrict__ cw,
                                               const float* __restrict__ cb) {
    int g = blockIdx.x * 256 + threadIdx.x;
    if (g >= LL*DI) return;
    int d = g % DI;
    int p = g / DI;
    int h = p >> 6, w = p & 63;
    float acc = cb[d];
    #pragma unroll
    for (int i = 0; i < 3; i++) {
        int hh = h + i - 1;
        if ((unsigned)hh < 64u) {
            #pragma unroll
            for (int j = 0; j < 3; j++) {
                int ww = w + j - 1;
                if ((unsigned)ww < 64u)
                    acc = fmaf(g_xx[(hh*64+ww)*DI + d], cw[d*9 + i*3 + j], acc);
            }
        }
    }
    float s = acc / (1.f + __expf(-acc));
    g_xc[p*DI + d] = s;
}

// ---------------- K3: per-position projections -> B, C, delta/dx/Dx ----------------
__global__ void __launch_bounds__(256) k3_proj(const float* __restrict__ dt_b,
                                               const float* __restrict__ Ds) {
    __shared__ float xT[DI*20];     // [c][p] stride 20
    __shared__ float vbuf[152*8];   // [row][p]
    int p0 = blockIdx.x * 8;
    int t = threadIdx.x;
    for (int i = t; i < DI*8; i += 256) {
        int c = i % DI, p = i / DI;
        xT[c*20 + p] = g_xc[(p0+p)*DI + c];
    }
    __syncthreads();
    if (t < 152) {
        float acc[8];
        #pragma unroll
        for (int j = 0; j < 8; j++) acc[j] = 0.f;
        for (int c = 0; c < DI; c++) {
            float w = g_WpT[c*152 + t];
            const float4* xv = (const float4*)&xT[c*20];
            #pragma unroll
            for (int j4 = 0; j4 < 2; j4++) {
                float4 v = xv[j4];
                acc[j4*4+0] = fmaf(w, v.x, acc[j4*4+0]);
                acc[j4*4+1] = fmaf(w, v.y, acc[j4*4+1]);
                acc[j4*4+2] = fmaf(w, v.z, acc[j4*4+2]);
                acc[j4*4+3] = fmaf(w, v.w, acc[j4*4+3]);
            }
        }
        #pragma unroll
        for (int p = 0; p < 8; p++) vbuf[t*8 + p] = acc[p];
        int k = t / 38, cc = t % 38;
        if (cc >= 6 && cc < 22) {
            #pragma unroll
            for (int p = 0; p < 8; p++) {
                int l = invperm(k, p0+p);
                g_Bs[((size_t)k*LL + l)*DSN + (cc-6)] = acc[p];
            }
        } else if (cc >= 22) {
            #pragma unroll
            for (int p = 0; p < 8; p++) {
                int l = invperm(k, p0+p);
                g_Cs[((size_t)k*LL + l)*DSN + (cc-22)] = acc[p];
            }
        }
    }
    __syncthreads();
    for (int r = t; r < 768; r += 256) {
        int k = r / DI, d = r % DI;
        float acc[8];
        #pragma unroll
        for (int j = 0; j < 8; j++) acc[j] = 0.f;
        #pragma unroll
        for (int c = 0; c < DRNK; c++) {
            float w = g_dtwT[c*768 + r];
            const float* vv = &vbuf[(k*38 + c)*8];
            #pragma unroll
            for (int p = 0; p < 8; p++) acc[p] = fmaf(w, vv[p], acc[p]);
        }
        float b = dt_b[r];
        float Dv = Ds[r];
        float dlt[8], dxv[8], Dxv[8];
        #pragma unroll
        for (int p = 0; p < 8; p++) {
            float xv = acc[p] + b;
            float sp = (xv > 20.f) ? xv : log1pf(__expf(xv));
            float xcv = xT[d*20 + p];
            dlt[p] = sp;
            dxv[p] = sp * xcv;
            Dxv[p] = Dv * xcv;
        }
        size_t o = (size_t)r*LL + p0;    // r == k*DI+d
        #pragma unroll
        for (int q = 0; q < 2; q++) {
            ((float4*)(g_dT  + o))[q] = ((float4*)dlt)[q];
            ((float4*)(g_dxT + o))[q] = ((float4*)dxv)[q];
            ((float4*)(g_DxT + o))[q] = ((float4*)Dxv)[q];
        }
    }
}

// ---------------- K4: two-pass segmented selective scan ----------------
// block = one (k,d) channel; 8 warps x 2 half-warps = 16 segments of 256 steps.
// lane n (0..15) = state index. Pass A: (P,q) per segment; serial combine; pass B: outputs.
__global__ void __launch_bounds__(256) k4_scan(const float* __restrict__ A_logs) {
    int kd = blockIdx.x;              // 0..767
    int k  = kd / DI;
    int t = threadIdx.x;
    int lane = t & 31, warp = t >> 5;
    int half = lane >> 4, n = lane & 15;
    int seg = warp*2 + half;
    float A2 = -__expf(A_logs[kd*DSN + n]) * 1.44269504f;  // A * log2(e)

    const float* dp  = g_dT  + (size_t)kd*LL;   // [p]
    const float* dxp = g_dxT + (size_t)kd*LL;
    const float* Dxp = g_DxT + (size_t)kd*LL;
    float*       yp  = g_yk  + (size_t)kd*LL;
    const float* bp  = g_Bs + (size_t)k*LL*DSN + n;  // [l*16]
    const float* cp  = g_Cs + (size_t)k*LL*DSN + n;

    __shared__ float sP[NSEG][DSN], sq[NSEG][DSN], shin[NSEG][DSN];

    // ---- pass A: per-segment transfer (P, q). seg 15's result is never needed.
    float P = 1.f, q = 0.f;
    if (seg != NSEG-1) {
        int l0 = seg * SEGL;
        for (int j0 = 0; j0 < SEGL; j0 += 8) {
            #pragma unroll
            for (int j = 0; j < 8; j++) {
                int l = l0 + j0 + j;
                int ll = (k >= 2) ? (LL-1-l) : l;
                int p  = (k & 1) ? (((ll & 63) << 6) | (ll >> 6)) : ll;
                float delta = __ldg(dp + p);
                float dxv   = __ldg(dxp + p);
                float bv    = __ldg(bp + l*DSN);
                float dA = ex2f(delta * A2);
                q = fmaf(dA, q, dxv * bv);
                P *= dA;
            }
        }
    }
    sP[seg][n] = P; sq[seg][n] = q;
    __syncthreads();
    if (t < DSN) {
        float h = 0.f;
        shin[0][t] = 0.f;
        #pragma unroll
        for (int s = 0; s < NSEG-1; s++) {
            h = fmaf(sP[s][t], h, sq[s][t]);
            shin[s+1][t] = h;
        }
    }
    __syncthreads();

    // ---- pass B
    float h = shin[seg][n];
    int l0 = seg * SEGL;
    for (int j0 = 0; j0 < SEGL; j0 += 8) {
        #pragma unroll
        for (int j = 0; j < 8; j++) {
            int l = l0 + j0 + j;
            int ll = (k >= 2) ? (LL-1-l) : l;
            int p  = (k & 1) ? (((ll & 63) << 6) | (ll >> 6)) : ll;
            float delta = __ldg(dp + p);
            float dxv   = __ldg(dxp + p);
            float bv    = __ldg(bp + l*DSN);
            float cv    = __ldg(cp + l*DSN);
            float dA = ex2f(delta * A2);
            h = fmaf(dA, h, dxv * bv);
            float part = h * cv;
            // 16-lane butterfly reduction (xor offsets stay within the half-warp)
            part += __shfl_xor_sync(0xffffffffu, part, 8);
            part += __shfl_xor_sync(0xffffffffu, part, 4);
            part += __shfl_xor_sync(0xffffffffu, part, 2);
            part += __shfl_xor_sync(0xffffffffu, part, 1);
            if (n == 0) yp[p] = part + __ldg(Dxp + p);
        }
    }
}

// ---------------- K5: combine 4 dirs + LayerNorm + SiLU gate + out_proj ----------------
__global__ void __launch_bounds__(256) k5_out(const float* __restrict__ ln_g,
                                              const float* __restrict__ ln_b,
                                              float* __restrict__ out) {
    __shared__ float ysm[8*200];  // [p][d] stride 200
    int p0 = blockIdx.x * 8;
    int t = threadIdx.x;
    for (int i = t; i < 8*DI; i += 256) {
        int d = i >> 3, p = i & 7;
        size_t o = (size_t)d*LL + p0 + p;
        float y = g_yk[o] + g_yk[(size_t)DI*LL + o]
                + g_yk[(size_t)2*DI*LL + o] + g_yk[(size_t)3*DI*LL + o];
        ysm[p*200 + d] = y;
    }
    __syncthreads();
    {
        int wp = t >> 5, ln = t & 31;   // 8 warps == 8 positions
        float s = 0.f, s2 = 0.f;
        for (int d = ln; d < DI; d += 32) {
            float v = ysm[wp*200 + d];
            s += v; s2 += v*v;
        }
        #pragma unroll
        for (int o = 16; o; o >>= 1) {
            s  += __shfl_xor_sync(0xffffffffu, s,  o);
            s2 += __shfl_xor_sync(0xffffffffu, s2, o);
        }
        float mu   = s  * (1.f/DI);
        float var  = s2 * (1.f/DI) - mu*mu;
        float rstd = rsqrtf(var + 1e-5f);
        for (int d = ln; d < DI; d += 32) {
            float v = (ysm[wp*200 + d] - mu) * rstd * ln_g[d] + ln_b[d];
            float z = g_z[(p0+wp)*DI + d];
            float sz = z / (1.f + __expf(-z));
            ysm[wp*200 + d] = v * sz;
        }
    }
    __syncthreads();
    for (int task = t; task < 96*8; task += 256) {
        int row = task % 96, p = task / 96;
        float acc = 0.f;
        const float* g = &ysm[p*200];
        #pragma unroll 4
        for (int d = 0; d < DI; d++)
            acc = fmaf(g_opT[d*96 + row], g[d], acc);
        out[(p0+p)*96 + row] = acc;
    }
}

extern "C" void kernel_launch(void* const* d_in, const int* in_sizes, int n_in,
                              void* d_out, int out_size) {
    const float* x         = (const float*)d_in[0];
    const float* in_proj_w = (const float*)d_in[1];
    const float* conv_w    = (const float*)d_in[2];
    const float* conv_b    = (const float*)d_in[3];
    const float* x_proj_w  = (const float*)d_in[4];
    const float* dt_w      = (const float*)d_in[5];
    const float* dt_b      = (const float*)d_in[6];
    const float* A_logs    = (const float*)d_in[7];
    const float* Ds        = (const float*)d_in[8];
    const float* ln_g      = (const float*)d_in[9];
    const float* ln_b      = (const float*)d_in[10];
    const float* out_proj  = (const float*)d_in[11];
    float* out = (float*)d_out;

    k0_prep<<<64, 256>>>(in_proj_w, x_proj_w, dt_w, out_proj);
    k1_inproj<<<LL/8, 384>>>(x);
    k2_conv<<<(LL*DI)/256, 256>>>(conv_w, conv_b);
    k3_proj<<<LL/8, 256>>>(dt_b, Ds);
    k4_scan<<<KDIR*DI, 256>>>(A_logs);
    k5_out<<<LL/8, 256>>>(ln_g, ln_b, out);
    (void)in_sizes; (void)n_in; (void)out_size;
}

// round 4
// speedup vs baseline: 2.9537x; 1.1449x over previous
#include <cuda_runtime.h>
#include <math.h>

#define LL   4096
#define DM   96
#define DI   192
#define DSN  16
#define DRNK 6
#define KDIR 4
#define NSEG 16
#define SEGL (LL/NSEG)   // 256

// ---- scratch (channel-major layouts) ----
__device__ float  g_xxT[DI*LL];        // [d][p] pre-conv
__device__ float  g_zT [DI*LL];        // [d][p] gate branch
__device__ float  g_xcT[DI*LL];        // [d][p] conv+silu
__device__ float2 g_ddx[KDIR*DI*LL];   // [kd][p] {delta, delta*x}
__device__ float2 g_BC [KDIR*LL*DSN];  // [k][l][n] {B, C} scan-ordered
__device__ float  g_yk [KDIR*DI*LL];   // [kd][p] per-direction y
__device__ float  g_in4 [DM*96*4];     // [c][rg][4]  in_proj rows rg*4+j
__device__ float  g_Wp4 [DI*38*4];     // [c][rg][4]  x_proj rows (152)
__device__ float  g_dtwT[DRNK*768];    // [r][kd]
__device__ float  g_op4 [DI*24*4];     // [c][rg][4]  out_proj rows (96)
__device__ float  g_sumD[DI];          // sum_k Ds[k][d]

__device__ __forceinline__ float ex2f(float x) {
    float r; asm("ex2.approx.ftz.f32 %0, %1;" : "=f"(r) : "f"(x)); return r;
}
__device__ __forceinline__ int invperm(int k, int p) {
    int t = ((p & 63) << 6) | (p >> 6);
    int l = (k & 1) ? t : p;
    return (k >= 2) ? (LL - 1 - l) : l;
}
__device__ __forceinline__ int posf(int k, int l) {
    int ll = (k >= 2) ? (LL - 1 - l) : l;
    return (k & 1) ? (((ll & 63) << 6) | (ll >> 6)) : ll;
}

// ---------------- K0: weight repacks ----------------
__global__ void k0_prep(const float* __restrict__ in_w, const float* __restrict__ xp_w,
                        const float* __restrict__ dt_w, const float* __restrict__ op_w,
                        const float* __restrict__ Ds) {
    int t = blockIdx.x * blockDim.x + threadIdx.x;
    int stride = gridDim.x * blockDim.x;
    for (int i = t; i < 384*DM; i += stride) {
        int e = i / DM, c = i % DM;
        g_in4[(c*96 + (e>>2))*4 + (e&3)] = in_w[e*DM + c];
    }
    for (int i = t; i < 152*DI; i += stride) {
        int e = i / DI, c = i % DI;
        g_Wp4[(c*38 + (e>>2))*4 + (e&3)] = xp_w[e*DI + c];
    }
    for (int i = t; i < 768*DRNK; i += stride) {
        int kd = i / DRNK, r = i % DRNK;
        g_dtwT[r*768 + kd] = dt_w[kd*DRNK + r];
    }
    for (int i = t; i < DM*DI; i += stride) {
        int e = i / DI, c = i % DI;
        g_op4[(c*24 + (e>>2))*4 + (e&3)] = op_w[e*DI + c];
    }
    for (int i = t; i < DI; i += stride)
        g_sumD[i] = Ds[i] + Ds[DI+i] + Ds[2*DI+i] + Ds[3*DI+i];
}

// ---------------- K1: in_proj, 16 positions/block, 4x4 register tile ----------------
__global__ void __launch_bounds__(384) k1_inproj(const float* __restrict__ x) {
    __shared__ float xs[96*20];   // [c][p] stride 20
    int p0 = blockIdx.x * 16;
    int t = threadIdx.x;
    for (int i = t; i < 16*96; i += 384) {
        int p = i / 96, c = i % 96;
        xs[c*20 + p] = __ldg(&x[(size_t)(p0+p)*DM + c]);
    }
    __syncthreads();
    int rg = t % 96, pg = t / 96;   // rows rg*4..+3, positions pg*4..+3
    float acc[16];
    #pragma unroll
    for (int j = 0; j < 16; j++) acc[j] = 0.f;
    const float4* w4 = (const float4*)g_in4;
    for (int c = 0; c < 96; c++) {
        float4 w = __ldg(&w4[c*96 + rg]);
        float4 xv = *(const float4*)&xs[c*20 + pg*4];
        acc[0]  = fmaf(w.x, xv.x, acc[0]);  acc[1]  = fmaf(w.x, xv.y, acc[1]);
        acc[2]  = fmaf(w.x, xv.z, acc[2]);  acc[3]  = fmaf(w.x, xv.w, acc[3]);
        acc[4]  = fmaf(w.y, xv.x, acc[4]);  acc[5]  = fmaf(w.y, xv.y, acc[5]);
        acc[6]  = fmaf(w.y, xv.z, acc[6]);  acc[7]  = fmaf(w.y, xv.w, acc[7]);
        acc[8]  = fmaf(w.z, xv.x, acc[8]);  acc[9]  = fmaf(w.z, xv.y, acc[9]);
        acc[10] = fmaf(w.z, xv.z, acc[10]); acc[11] = fmaf(w.z, xv.w, acc[11]);
        acc[12] = fmaf(w.w, xv.x, acc[12]); acc[13] = fmaf(w.w, xv.y, acc[13]);
        acc[14] = fmaf(w.w, xv.z, acc[14]); acc[15] = fmaf(w.w, xv.w, acc[15]);
    }
    #pragma unroll
    for (int j = 0; j < 4; j++) {
        int row = rg*4 + j;
        float4 v = make_float4(acc[j*4], acc[j*4+1], acc[j*4+2], acc[j*4+3]);
        if (row < DI) *(float4*)&g_xxT[(size_t)row*LL + p0 + pg*4] = v;
        else          *(float4*)&g_zT[(size_t)(row-DI)*LL + p0 + pg*4] = v;
    }
}

// ---------------- K2: depthwise 3x3 conv + bias + SiLU (channel-major, coalesced) ----------------
__global__ void __launch_bounds__(256) k2_conv(const float* __restrict__ cw,
                                               const float* __restrict__ cb) {
    int i = blockIdx.x * 256 + threadIdx.x;   // 192*4096
    int d = i >> 12, p = i & 4095;
    int h = p >> 6, w = p & 63;
    const float* base = g_xxT + (size_t)d*LL;
    float acc = __ldg(&cb[d]);
    #pragma unroll
    for (int di = -1; di <= 1; di++) {
        int hh = h + di;
        if ((unsigned)hh < 64u) {
            #pragma unroll
            for (int dj = -1; dj <= 1; dj++) {
                int ww = w + dj;
                if ((unsigned)ww < 64u)
                    acc = fmaf(base[p + di*64 + dj], __ldg(&cw[d*9 + (di+1)*3 + (dj+1)]), acc);
            }
        }
    }
    g_xcT[(size_t)d*LL + p] = acc / (1.f + __expf(-acc));
}

// ---------------- K3: projections -> BC (scan-ordered), ddx (channel-major) ----------------
// 16 positions/block, 320 threads. Stage1: split-K 4x4 tiles. Stage2: rank-6 delta.
__global__ void __launch_bounds__(320) k3_proj(const float* __restrict__ dt_b) {
    __shared__ float xs[DI*16];       // [c][p] stride 16
    __shared__ float vbuf[152*20];    // [row][p] stride 20
    __shared__ float vred[152*20];
    int p0 = blockIdx.x * 16;
    int t = threadIdx.x;
    for (int i = t; i < DI*16; i += 320) {
        int c = i >> 4, p = i & 15;
        xs[i] = __ldg(&g_xcT[(size_t)c*LL + p0 + p]);
    }
    __syncthreads();

    // stage1: v[152 rows][16 pos] = Wp @ xc, split over 2 c-halves
    float acc[16];
    #pragma unroll
    for (int j = 0; j < 16; j++) acc[j] = 0.f;
    int ch = 0, rg = 0, pg = 0;
    if (t < 304) {
        ch = t / 152; int rem = t % 152;
        rg = rem % 38; pg = rem / 38;
        const float4* w4 = (const float4*)g_Wp4;
        for (int cl = 0; cl < 96; cl++) {
            int c = ch*96 + cl;
            float4 w = __ldg(&w4[c*38 + rg]);
            float4 xv = *(const float4*)&xs[c*16 + pg*4];
            acc[0]  = fmaf(w.x, xv.x, acc[0]);  acc[1]  = fmaf(w.x, xv.y, acc[1]);
            acc[2]  = fmaf(w.x, xv.z, acc[2]);  acc[3]  = fmaf(w.x, xv.w, acc[3]);
            acc[4]  = fmaf(w.y, xv.x, acc[4]);  acc[5]  = fmaf(w.y, xv.y, acc[5]);
            acc[6]  = fmaf(w.y, xv.z, acc[6]);  acc[7]  = fmaf(w.y, xv.w, acc[7]);
            acc[8]  = fmaf(w.z, xv.x, acc[8]);  acc[9]  = fmaf(w.z, xv.y, acc[9]);
            acc[10] = fmaf(w.z, xv.z, acc[10]); acc[11] = fmaf(w.z, xv.w, acc[11]);
            acc[12] = fmaf(w.w, xv.x, acc[12]); acc[13] = fmaf(w.w, xv.y, acc[13]);
            acc[14] = fmaf(w.w, xv.z, acc[14]); acc[15] = fmaf(w.w, xv.w, acc[15]);
        }
        if (ch == 1) {
            #pragma unroll
            for (int j = 0; j < 4; j++)
                *(float4*)&vred[(rg*4+j)*20 + pg*4] =
                    make_float4(acc[j*4], acc[j*4+1], acc[j*4+2], acc[j*4+3]);
        }
    }
    __syncthreads();
    if (t < 152) {   // ch == 0
        #pragma unroll
        for (int j = 0; j < 4; j++) {
            float4 r = *(const float4*)&vred[(rg*4+j)*20 + pg*4];
            *(float4*)&vbuf[(rg*4+j)*20 + pg*4] =
                make_float4(acc[j*4]+r.x, acc[j*4+1]+r.y, acc[j*4+2]+r.z, acc[j*4+3]+r.w);
        }
    }
    __syncthreads();

    // B/C scatter to scan-ordered interleaved {B,C}
    if (t < 256) {
        int k = t >> 6, rest = t & 63;
        int cc = 6 + (rest >> 1);
        int ph = rest & 1;
        int n_ = cc - 6;
        int slot = (n_ < 16) ? 0 : 1;
        int n = slot ? (n_ - 16) : n_;
        const float* vrow = &vbuf[(k*38 + cc)*20 + ph*8];
        float* BCf = (float*)g_BC;
        #pragma unroll
        for (int p = 0; p < 8; p++) {
            int l = invperm(k, p0 + ph*8 + p);
            BCf[(((size_t)k*LL + l)*DSN + n)*2 + slot] = vrow[p];
        }
    }

    // stage2: delta = softplus(dtw . v[k,0:6] + b); pack {delta, delta*x}
    for (int task = t; task < 1536; task += 320) {
        int r = task % 768, ph = task / 768;
        int k = r / DI, d = r % DI;
        float a8[8];
        #pragma unroll
        for (int p = 0; p < 8; p++) a8[p] = 0.f;
        #pragma unroll
        for (int c = 0; c < DRNK; c++) {
            float w = __ldg(&g_dtwT[c*768 + r]);
            const float4* vrow = (const float4*)&vbuf[(k*38 + c)*20 + ph*8];
            float4 v0 = vrow[0], v1 = vrow[1];
            a8[0] = fmaf(w, v0.x, a8[0]); a8[1] = fmaf(w, v0.y, a8[1]);
            a8[2] = fmaf(w, v0.z, a8[2]); a8[3] = fmaf(w, v0.w, a8[3]);
            a8[4] = fmaf(w, v1.x, a8[4]); a8[5] = fmaf(w, v1.y, a8[5]);
            a8[6] = fmaf(w, v1.z, a8[6]); a8[7] = fmaf(w, v1.w, a8[7]);
        }
        float bb = __ldg(&dt_b[r]);
        float sp8[8], dx8[8];
        #pragma unroll
        for (int p = 0; p < 8; p++) {
            float xv = a8[p] + bb;
            float sp = (xv > 15.f) ? xv : __logf(1.f + __expf(xv));
            float xc = xs[d*16 + ph*8 + p];
            sp8[p] = sp; dx8[p] = sp * xc;
        }
        float4* dst = (float4*)&g_ddx[(size_t)r*LL + p0 + ph*8];
        #pragma unroll
        for (int m = 0; m < 4; m++)
            dst[m] = make_float4(sp8[2*m], dx8[2*m], sp8[2*m+1], dx8[2*m+1]);
    }
}

// ---------------- K4: two-pass segmented scan, 8-lane groups, 2 states/lane ----------------
__global__ void __launch_bounds__(256) k4_scan(const float* __restrict__ A_logs) {
    int t = threadIdx.x;
    int g = t >> 3, q = t & 7;
    int ch = g >> 4, seg = g & 15;
    int kd = blockIdx.x * 2 + ch;
    int k  = kd / DI;
    float A2a = -__expf(__ldg(&A_logs[kd*DSN + q]))     * 1.44269504f;
    float A2b = -__expf(__ldg(&A_logs[kd*DSN + q + 8])) * 1.44269504f;
    const float2* ddx = g_ddx + (size_t)kd*LL;
    const float2* bc  = g_BC + (size_t)k*LL*DSN;
    float* yp = g_yk + (size_t)kd*LL;
    int sp = (k == 0) ? 1 : (k == 1) ? 64 : (k == 2) ? -1 : -64;

    __shared__ float sP[2][NSEG][DSN], sQ[2][NSEG][DSN], shin[2][NSEG][DSN];

    float Pa = 1.f, Pb = 1.f, Qa = 0.f, Qb = 0.f;
    if (seg != NSEG-1) {
        int l0 = seg * SEGL;
        for (int j0 = 0; j0 < SEGL; j0 += 8) {
            int lb = l0 + j0;
            int pb = posf(k, lb);
            #pragma unroll
            for (int j = 0; j < 8; j++) {
                float2 dd = __ldg(&ddx[pb + j*sp]);
                float2 ba = __ldg(&bc[(size_t)(lb+j)*DSN + q]);
                float2 bv = __ldg(&bc[(size_t)(lb+j)*DSN + q + 8]);
                float ea = ex2f(dd.x * A2a), eb = ex2f(dd.x * A2b);
                Qa = fmaf(ea, Qa, dd.y * ba.x);
                Qb = fmaf(eb, Qb, dd.y * bv.x);
                Pa *= ea; Pb *= eb;
            }
        }
    }
    sP[ch][seg][q] = Pa; sP[ch][seg][q+8] = Pb;
    sQ[ch][seg][q] = Qa; sQ[ch][seg][q+8] = Qb;
    __syncthreads();
    if (t < 32) {
        int c2 = t >> 4, n = t & 15;
        float h = 0.f;
        shin[c2][0][n] = 0.f;
        #pragma unroll
        for (int s = 0; s < NSEG-1; s++) {
            h = fmaf(sP[c2][s][n], h, sQ[c2][s][n]);
            shin[c2][s+1][n] = h;
        }
    }
    __syncthreads();

    float ha = shin[ch][seg][q], hb = shin[ch][seg][q+8];
    int l0 = seg * SEGL;
    for (int j0 = 0; j0 < SEGL; j0 += 8) {
        int lb = l0 + j0;
        int pb = posf(k, lb);
        #pragma unroll
        for (int j = 0; j < 8; j++) {
            int p = pb + j*sp;
            float2 dd = __ldg(&ddx[p]);
            float2 ba = __ldg(&bc[(size_t)(lb+j)*DSN + q]);
            float2 bv = __ldg(&bc[(size_t)(lb+j)*DSN + q + 8]);
            float ea = ex2f(dd.x * A2a), eb = ex2f(dd.x * A2b);
            ha = fmaf(ea, ha, dd.y * ba.x);
            hb = fmaf(eb, hb, dd.y * bv.x);
            float part = fmaf(ha, ba.y, hb * bv.y);
            part += __shfl_xor_sync(0xffffffffu, part, 4);
            part += __shfl_xor_sync(0xffffffffu, part, 2);
            part += __shfl_xor_sync(0xffffffffu, part, 1);
            if (q == 0) yp[p] = part;
        }
    }
}

// ---------------- K5: combine + sumD*x + LN + SiLU gate + out_proj ----------------
__global__ void __launch_bounds__(256) k5_out(const float* __restrict__ ln_g,
                                              const float* __restrict__ ln_b,
                                              float* __restrict__ out) {
    __shared__ float ysm[DI*16];     // [d][p] stride 16
    __shared__ float ps[16*16], ps2[16*16];
    __shared__ float mus[16], rstds[16];
    __shared__ float red[96*20];
    int p0 = blockIdx.x * 16;
    int t = threadIdx.x;
    for (int i = t; i < DI*16; i += 256) {
        int d = i >> 4, p = i & 15;
        size_t o = (size_t)d*LL + p0 + p;
        float y = g_yk[o] + g_yk[(size_t)DI*LL + o]
                + g_yk[(size_t)2*DI*LL + o] + g_yk[(size_t)3*DI*LL + o]
                + g_sumD[d] * g_xcT[o];
        ysm[i] = y;
    }
    __syncthreads();
    {
        int p = t & 15, grp = t >> 4;
        float s = 0.f, s2 = 0.f;
        #pragma unroll
        for (int dd = 0; dd < 12; dd++) {
            float v = ysm[(grp*12 + dd)*16 + p];
            s += v; s2 += v*v;
        }
        ps[grp*16 + p] = s; ps2[grp*16 + p] = s2;
    }
    __syncthreads();
    if (t < 16) {
        float s = 0.f, s2 = 0.f;
        #pragma unroll
        for (int gp = 0; gp < 16; gp++) { s += ps[gp*16 + t]; s2 += ps2[gp*16 + t]; }
        float mu = s * (1.f/DI);
        float var = s2 * (1.f/DI) - mu*mu;
        mus[t] = mu; rstds[t] = rsqrtf(var + 1e-5f);
    }
    __syncthreads();
    for (int i = t; i < DI*16; i += 256) {
        int d = i >> 4, p = i & 15;
        float v = (ysm[i] - mus[p]) * rstds[p] * __ldg(&ln_g[d]) + __ldg(&ln_b[d]);
        float z = g_zT[(size_t)d*LL + p0 + p];
        ysm[i] = v * (z / (1.f + __expf(-z)));
    }
    __syncthreads();
    // out_proj: 96 rows, split-K over 2 c-halves, 4x4 tiles
    float acc[16];
    #pragma unroll
    for (int j = 0; j < 16; j++) acc[j] = 0.f;
    int ch = 0, rg = 0, pg = 0;
    if (t < 192) {
        ch = t / 96; int rem = t % 96;
        rg = rem % 24; pg = rem / 24;
        const float4* w4 = (const float4*)g_op4;
        for (int cl = 0; cl < 96; cl++) {
            int c = ch*96 + cl;
            float4 w = __ldg(&w4[c*24 + rg]);
            float4 xv = *(const float4*)&ysm[c*16 + pg*4];
            acc[0]  = fmaf(w.x, xv.x, acc[0]);  acc[1]  = fmaf(w.x, xv.y, acc[1]);
            acc[2]  = fmaf(w.x, xv.z, acc[2]);  acc[3]  = fmaf(w.x, xv.w, acc[3]);
            acc[4]  = fmaf(w.y, xv.x, acc[4]);  acc[5]  = fmaf(w.y, xv.y, acc[5]);
            acc[6]  = fmaf(w.y, xv.z, acc[6]);  acc[7]  = fmaf(w.y, xv.w, acc[7]);
            acc[8]  = fmaf(w.z, xv.x, acc[8]);  acc[9]  = fmaf(w.z, xv.y, acc[9]);
            acc[10] = fmaf(w.z, xv.z, acc[10]); acc[11] = fmaf(w.z, xv.w, acc[11]);
            acc[12] = fmaf(w.w, xv.x, acc[12]); acc[13] = fmaf(w.w, xv.y, acc[13]);
            acc[14] = fmaf(w.w, xv.z, acc[14]); acc[15] = fmaf(w.w, xv.w, acc[15]);
        }
    }
    __syncthreads();
    if (t < 192 && ch == 1) {
        #pragma unroll
        for (int j = 0; j < 4; j++)
            *(float4*)&red[(rg*4+j)*20 + pg*4] =
                make_float4(acc[j*4], acc[j*4+1], acc[j*4+2], acc[j*4+3]);
    }
    __syncthreads();
    if (t < 96) {   // ch == 0
        float r[16];
        #pragma unroll
        for (int j = 0; j < 4; j++) {
            float4 rv = *(const float4*)&red[(rg*4+j)*20 + pg*4];
            r[j*4] = rv.x; r[j*4+1] = rv.y; r[j*4+2] = rv.z; r[j*4+3] = rv.w;
        }
        #pragma unroll
        for (int pi = 0; pi < 4; pi++) {
            float4 v = make_float4(acc[0*4+pi] + r[0*4+pi], acc[1*4+pi] + r[1*4+pi],
                                   acc[2*4+pi] + r[2*4+pi], acc[3*4+pi] + r[3*4+pi]);
            *(float4*)&out[(size_t)(p0 + pg*4 + pi)*DM + rg*4] = v;
        }
    }
}

extern "C" void kernel_launch(void* const* d_in, const int* in_sizes, int n_in,
                              void* d_out, int out_size) {
    const float* x         = (const float*)d_in[0];
    const float* in_proj_w = (const float*)d_in[1];
    const float* conv_w    = (const float*)d_in[2];
    const float* conv_b    = (const float*)d_in[3];
    const float* x_proj_w  = (const float*)d_in[4];
    const float* dt_w      = (const float*)d_in[5];
    const float* dt_b      = (const float*)d_in[6];
    const float* A_logs    = (const float*)d_in[7];
    const float* Ds        = (const float*)d_in[8];
    const float* ln_g      = (const float*)d_in[9];
    const float* ln_b      = (const float*)d_in[10];
    const float* out_proj  = (const float*)d_in[11];
    float* out = (float*)d_out;

    k0_prep<<<64, 256>>>(in_proj_w, x_proj_w, dt_w, out_proj, Ds);
    k1_inproj<<<LL/16, 384>>>(x);
    k2_conv<<<(DI*LL)/256, 256>>>(conv_w, conv_b);
    k3_proj<<<LL/16, 320>>>(dt_b);
    k4_scan<<<KDIR*DI/2, 256>>>(A_logs);
    k5_out<<<LL/16, 256>>>(ln_g, ln_b, out);
    (void)in_sizes; (void)n_in; (void)out_size;
}